// round 5
// baseline (speedup 1.0000x reference)
#include <cuda_runtime.h>
#include <cuda_bf16.h>
#include <math.h>
#include <stdint.h>

// ---------------- problem constants ----------------
#define DIMN     1024
#define HEADS    16
#define HEAD_DIM 64
#define LAYERS   4
#define HIDDEN   4096
#define VOCAB    32000
#define BATCH    2
#define SEQ      1024
#define MTOK     (BATCH*SEQ)
#define EPS      1e-6f

// ---------------- fp32 scratch ----------------
__device__ float g_h   [MTOK*DIMN];
__device__ float g_att [(size_t)BATCH*HEADS*SEQ*SEQ];
__device__ float g_gate[MTOK*HIDDEN];
__device__ float g_up  [MTOK*HIDDEN];

// ---------------- bf16 hi/lo planes (activations) ----------------
__device__ __nv_bfloat16 g_xh[MTOK*DIMN],  g_xl[MTOK*DIMN];
__device__ __nv_bfloat16 g_qh[MTOK*DIMN],  g_ql[MTOK*DIMN];
__device__ __nv_bfloat16 g_kh[MTOK*DIMN],  g_kl[MTOK*DIMN];
__device__ __nv_bfloat16 g_vh[MTOK*DIMN],  g_vl[MTOK*DIMN];
__device__ __nv_bfloat16 g_vth[MTOK*DIMN], g_vtl[MTOK*DIMN];
__device__ __nv_bfloat16 g_yh[MTOK*DIMN],  g_yl[MTOK*DIMN];
__device__ __nv_bfloat16 g_ath[(size_t)BATCH*HEADS*SEQ*SEQ];
__device__ __nv_bfloat16 g_atl[(size_t)BATCH*HEADS*SEQ*SEQ];
__device__ __nv_bfloat16 g_gh[MTOK*HIDDEN], g_gl[MTOK*HIDDEN];

// ---------------- bf16 hi/lo planes (weights) ----------------
__device__ __nv_bfloat16 g_wq_h[LAYERS*DIMN*DIMN],  g_wq_l[LAYERS*DIMN*DIMN];
__device__ __nv_bfloat16 g_wk_h[LAYERS*DIMN*DIMN],  g_wk_l[LAYERS*DIMN*DIMN];
__device__ __nv_bfloat16 g_wv_h[LAYERS*DIMN*DIMN],  g_wv_l[LAYERS*DIMN*DIMN];
__device__ __nv_bfloat16 g_wo_h[LAYERS*DIMN*DIMN],  g_wo_l[LAYERS*DIMN*DIMN];
__device__ __nv_bfloat16 g_wg_h[LAYERS*HIDDEN*DIMN], g_wg_l[LAYERS*HIDDEN*DIMN];
__device__ __nv_bfloat16 g_wu_h[LAYERS*HIDDEN*DIMN], g_wu_l[LAYERS*HIDDEN*DIMN];
__device__ __nv_bfloat16 g_wd_h[LAYERS*DIMN*HIDDEN], g_wd_l[LAYERS*DIMN*HIDDEN];
__device__ __nv_bfloat16 g_lm_h[(size_t)VOCAB*DIMN], g_lm_l[(size_t)VOCAB*DIMN];

// ---------------- helpers ----------------
__device__ __forceinline__ uint32_t smem_u32(const void* p) {
    uint32_t a;
    asm("{ .reg .u64 t; cvta.to.shared.u64 t, %1; cvt.u32.u64 %0, t; }"
        : "=r"(a) : "l"(p));
    return a;
}
__device__ __forceinline__ void cp16(uint32_t s, const void* g) {
    asm volatile("cp.async.cg.shared.global [%0], [%1], 16;" :: "r"(s), "l"(g));
}
#define CP_COMMIT() asm volatile("cp.async.commit_group;" ::: "memory")
#define CP_WAIT2()  asm volatile("cp.async.wait_group 2;" ::: "memory")

__device__ __forceinline__ void ldm4(uint32_t* r, uint32_t addr) {
    asm volatile("ldmatrix.sync.aligned.m8n8.x4.shared.b16 {%0,%1,%2,%3}, [%4];"
                 : "=r"(r[0]), "=r"(r[1]), "=r"(r[2]), "=r"(r[3]) : "r"(addr));
}
__device__ __forceinline__ void mma16816(float* c, const uint32_t* a, const uint32_t* b) {
    asm volatile("mma.sync.aligned.m16n8k16.row.col.f32.bf16.bf16.f32 "
                 "{%0,%1,%2,%3}, {%4,%5,%6,%7}, {%8,%9}, {%0,%1,%2,%3};"
                 : "+f"(c[0]), "+f"(c[1]), "+f"(c[2]), "+f"(c[3])
                 : "r"(a[0]), "r"(a[1]), "r"(a[2]), "r"(a[3]),
                   "r"(b[0]), "r"(b[1]));
}
__device__ __forceinline__ uint32_t pk_hi(float a, float b) {
    return __byte_perm(__float_as_uint(a), __float_as_uint(b), 0x7632);
}
__device__ __forceinline__ uint32_t pk_lo(float a, float b) {
    float la = a - __uint_as_float(__float_as_uint(a) & 0xFFFF0000u);
    float lb = b - __uint_as_float(__float_as_uint(b) & 0xFFFF0000u);
    return __byte_perm(__float_as_uint(la), __float_as_uint(lb), 0x7632);
}

// ---------------- weight splitter ----------------
__global__ void split_kernel(const float4* __restrict__ in,
                             uint2* __restrict__ hi, uint2* __restrict__ lo)
{
    long i = (long)blockIdx.x * 256 + threadIdx.x;
    float4 f = in[i];
    hi[i] = make_uint2(pk_hi(f.x, f.y), pk_hi(f.z, f.w));
    lo[i] = make_uint2(pk_lo(f.x, f.y), pk_lo(f.z, f.w));
}

// ================= pipelined bf16-plane GEMM ==============================
// C = alpha * A * B^T [+C].  A/B given as hi/lo bf16 planes, row-major k-contig.
// CTA tile 128 x BN, BK=32, 256 threads (8 warps 2m x 4n), 4-stage cp.async.
// OMODE: 0 = fp32 store, 1 = fp32 accumulate, 2 = write hi/lo bf16 planes.
template<int BN, int OMODE>
__global__ void __launch_bounds__(256, 1)
bf_gemm(const __nv_bfloat16* __restrict__ Ah, const __nv_bfloat16* __restrict__ Al,
        int lda, long sAb, long sAh,
        const __nv_bfloat16* __restrict__ Bh, const __nv_bfloat16* __restrict__ Bl,
        int ldb, long sBb, long sBh,
        void* C0, void* C1, int ldc, long sCb, long sCh,
        int K, float alpha, int hdiv)
{
    constexpr int WN    = BN / 4;
    constexpr int NA    = WN / 8;
    constexpr int B_HI  = 16384;
    constexpr int BLO_D = BN * 64;
    constexpr int STAGE = 16384 + BN * 128;

    extern __shared__ char smem[];
    const uint32_t sb0 = smem_u32(smem);

    const int tid = threadIdx.x, lane = tid & 31, wid = tid >> 5;
    const int wm = wid & 1, wn = wid >> 1;

    const int z = blockIdx.z;
    const long aoff = (z / hdiv) * sAb + (z % hdiv) * sAh;
    const long boff = (z / hdiv) * sBb + (z % hdiv) * sBh;
    const long coff = (z / hdiv) * sCb + (z % hdiv) * sCh;
    Ah += aoff; Al += aoff;
    Bh += boff; Bl += boff;

    const int m0 = blockIdx.x * 128;
    const int n0 = blockIdx.y * BN;

    // ldmatrix offsets (stage-relative) — identical mapping to validated R4
    uint32_t offA[4][2], offB[NA / 2][2];
    #pragma unroll
    for (int am = 0; am < 4; am++)
        #pragma unroll
        for (int kk = 0; kk < 2; kk++) {
            int mrow  = wm * 64 + am * 16 + (lane & 7) + ((lane >> 3) & 1) * 8;
            int chunk = kk * 2 + ((lane >> 4) & 1);
            offA[am][kk] = (uint32_t)(mrow * 64 + ((chunk ^ ((mrow >> 1) & 3)) << 4));
        }
    #pragma unroll
    for (int p = 0; p < NA / 2; p++)
        #pragma unroll
        for (int kk = 0; kk < 2; kk++) {
            int nrow  = wn * WN + p * 16 + (lane & 7) + ((lane >> 4) & 1) * 8;
            int chunk = kk * 2 + ((lane >> 3) & 1);
            offB[p][kk] = (uint32_t)(B_HI + nrow * 64 + ((chunk ^ ((nrow >> 1) & 3)) << 4));
        }

    float acc[4][NA][4];
    #pragma unroll
    for (int i = 0; i < 4; i++)
        #pragma unroll
        for (int j = 0; j < NA; j++)
            #pragma unroll
            for (int e = 0; e < 4; e++) acc[i][j][e] = 0.0f;

    auto ISSUE = [&](int s) {
        const uint32_t sb = sb0 + (uint32_t)(s & 3) * STAGE;
        const int k0 = s * 32;
        #pragma unroll
        for (int i = 0; i < 2; i++) {                       // A: 512 chunks/plane
            int idx = i * 256 + tid, row = idx >> 2, ch = idx & 3;
            uint32_t d = sb + row * 64 + ((ch ^ ((row >> 1) & 3)) << 4);
            long g = (long)(m0 + row) * lda + k0 + ch * 8;
            cp16(d, Ah + g);
            cp16(d + 8192, Al + g);
        }
        #pragma unroll
        for (int i = 0; i < BN / 64; i++) {                 // B: BN*4 chunks/plane
            int idx = i * 256 + tid, row = idx >> 2, ch = idx & 3;
            uint32_t d = sb + B_HI + row * 64 + ((ch ^ ((row >> 1) & 3)) << 4);
            long g = (long)(n0 + row) * ldb + k0 + ch * 8;
            cp16(d, Bh + g);
            cp16(d + BLO_D, Bl + g);
        }
    };

    const int nk = K >> 5;
    #pragma unroll
    for (int s = 0; s < 3; s++) { if (s < nk) ISSUE(s); CP_COMMIT(); }

    for (int t = 0; t < nk; t++) {
        CP_WAIT2();
        __syncthreads();
        const uint32_t sb = sb0 + (uint32_t)(t & 3) * STAGE;

        #pragma unroll
        for (int kk = 0; kk < 2; kk++) {
            uint32_t ah[4][4], al[4][4];
            #pragma unroll
            for (int am = 0; am < 4; am++) {
                ldm4(ah[am], sb + offA[am][kk]);
                ldm4(al[am], sb + offA[am][kk] + 8192);
            }
            uint32_t bh[NA / 2][4], bl[NA / 2][4];
            #pragma unroll
            for (int p = 0; p < NA / 2; p++) {
                ldm4(bh[p], sb + offB[p][kk]);
                ldm4(bl[p], sb + offB[p][kk] + BLO_D);
            }
            #pragma unroll
            for (int am = 0; am < 4; am++)
                #pragma unroll
                for (int na = 0; na < NA; na++) {
                    const uint32_t* bhp = &bh[na >> 1][(na & 1) * 2];
                    const uint32_t* blp = &bl[na >> 1][(na & 1) * 2];
                    mma16816(acc[am][na], ah[am], bhp);
                    mma16816(acc[am][na], ah[am], blp);
                    mma16816(acc[am][na], al[am], bhp);
                }
        }

        __syncthreads();
        if (t + 3 < nk) ISSUE(t + 3);
        CP_COMMIT();
    }

    // ---------------- epilogue ----------------
    #pragma unroll
    for (int am = 0; am < 4; am++)
        #pragma unroll
        for (int na = 0; na < NA; na++) {
            int row = m0 + wm * 64 + am * 16 + (lane >> 2);
            int col = n0 + wn * WN + na * 8 + (lane & 3) * 2;
            float2 r0 = { alpha * acc[am][na][0], alpha * acc[am][na][1] };
            float2 r1 = { alpha * acc[am][na][2], alpha * acc[am][na][3] };
            if (OMODE <= 1) {
                float* Cf = (float*)C0 + coff;
                float* b0 = &Cf[(long)row * ldc + col];
                float* b1 = &Cf[(long)(row + 8) * ldc + col];
                if (OMODE == 1) {
                    float2 o0 = *(float2*)b0, o1 = *(float2*)b1;
                    r0.x += o0.x; r0.y += o0.y; r1.x += o1.x; r1.y += o1.y;
                }
                *(float2*)b0 = r0;
                *(float2*)b1 = r1;
            } else {
                __nv_bfloat16* Ch = (__nv_bfloat16*)C0 + coff;
                __nv_bfloat16* Cl = (__nv_bfloat16*)C1 + coff;
                long i0 = (long)row * ldc + col, i1 = (long)(row + 8) * ldc + col;
                *(uint32_t*)&Ch[i0] = pk_hi(r0.x, r0.y);
                *(uint32_t*)&Cl[i0] = pk_lo(r0.x, r0.y);
                *(uint32_t*)&Ch[i1] = pk_hi(r1.x, r1.y);
                *(uint32_t*)&Cl[i1] = pk_lo(r1.x, r1.y);
            }
        }
}

// ---------------- elementwise kernels ----------------
__global__ void embed_kernel(const int* __restrict__ tokens,
                             const float* __restrict__ embed,
                             float* __restrict__ h)
{
    int row = blockIdx.x;
    int tok = tokens[row];
    ((float4*)(h + (long)row * DIMN))[threadIdx.x] =
        ((const float4*)(embed + (long)tok * DIMN))[threadIdx.x];
}

// rmsnorm fp32 -> bf16 hi/lo planes
__global__ void rmsnorm_bf(const float* __restrict__ x, const float* __restrict__ w,
                           __nv_bfloat16* __restrict__ oh, __nv_bfloat16* __restrict__ ol)
{
    int row = blockIdx.x;
    float4 v = ((const float4*)(x + (long)row * DIMN))[threadIdx.x];
    float ss = v.x*v.x + v.y*v.y + v.z*v.z + v.w*v.w;
    __shared__ float red[8];
    #pragma unroll
    for (int o = 16; o > 0; o >>= 1) ss += __shfl_xor_sync(0xFFFFFFFFu, ss, o);
    if ((threadIdx.x & 31) == 0) red[threadIdx.x >> 5] = ss;
    __syncthreads();
    if (threadIdx.x < 8) {
        float s = red[threadIdx.x];
        #pragma unroll
        for (int o = 4; o > 0; o >>= 1) s += __shfl_xor_sync(0xFFu, s, o);
        if (threadIdx.x == 0) red[0] = s;
    }
    __syncthreads();
    float sc = rsqrtf(red[0] * (1.0f / DIMN) + EPS);
    float4 wv = ((const float4*)w)[threadIdx.x];
    float a = v.x*sc*wv.x, b = v.y*sc*wv.y, c = v.z*sc*wv.z, d = v.w*sc*wv.w;
    ((uint2*)(oh + (long)row * DIMN))[threadIdx.x] = make_uint2(pk_hi(a,b), pk_hi(c,d));
    ((uint2*)(ol + (long)row * DIMN))[threadIdx.x] = make_uint2(pk_lo(a,b), pk_lo(c,d));
}

// softmax fp32 -> bf16 hi/lo planes
__global__ void softmax_bf(const float* __restrict__ att,
                           __nv_bfloat16* __restrict__ oh, __nv_bfloat16* __restrict__ ol)
{
    long row = blockIdx.x;
    const float4* p = (const float4*)(att + row * (long)SEQ);
    float4 v = p[threadIdx.x];
    __shared__ float red[8];
    float mx = fmaxf(fmaxf(v.x, v.y), fmaxf(v.z, v.w));
    #pragma unroll
    for (int o = 16; o > 0; o >>= 1) mx = fmaxf(mx, __shfl_xor_sync(0xFFFFFFFFu, mx, o));
    if ((threadIdx.x & 31) == 0) red[threadIdx.x >> 5] = mx;
    __syncthreads();
    if (threadIdx.x < 8) {
        float s = red[threadIdx.x];
        #pragma unroll
        for (int o = 4; o > 0; o >>= 1) s = fmaxf(s, __shfl_xor_sync(0xFFu, s, o));
        if (threadIdx.x == 0) red[0] = s;
    }
    __syncthreads();
    mx = red[0];
    __syncthreads();
    v.x = expf(v.x - mx); v.y = expf(v.y - mx);
    v.z = expf(v.z - mx); v.w = expf(v.w - mx);
    float sum = v.x + v.y + v.z + v.w;
    #pragma unroll
    for (int o = 16; o > 0; o >>= 1) sum += __shfl_xor_sync(0xFFFFFFFFu, sum, o);
    if ((threadIdx.x & 31) == 0) red[threadIdx.x >> 5] = sum;
    __syncthreads();
    if (threadIdx.x < 8) {
        float s = red[threadIdx.x];
        #pragma unroll
        for (int o = 4; o > 0; o >>= 1) s += __shfl_xor_sync(0xFFu, s, o);
        if (threadIdx.x == 0) red[0] = s;
    }
    __syncthreads();
    float inv = 1.0f / red[0];
    v.x *= inv; v.y *= inv; v.z *= inv; v.w *= inv;
    ((uint2*)(oh + row * (long)SEQ))[threadIdx.x] = make_uint2(pk_hi(v.x,v.y), pk_hi(v.z,v.w));
    ((uint2*)(ol + row * (long)SEQ))[threadIdx.x] = make_uint2(pk_lo(v.x,v.y), pk_lo(v.z,v.w));
}

// silu(gate)*up fp32 -> bf16 hi/lo planes
__global__ void silu_bf(const float4* __restrict__ g, const float4* __restrict__ u,
                        __nv_bfloat16* __restrict__ oh, __nv_bfloat16* __restrict__ ol)
{
    long i = (long)blockIdx.x * blockDim.x + threadIdx.x;
    float4 gv = g[i], uv = u[i];
    float a = gv.x / (1.0f + expf(-gv.x)) * uv.x;
    float b = gv.y / (1.0f + expf(-gv.y)) * uv.y;
    float c = gv.z / (1.0f + expf(-gv.z)) * uv.z;
    float d = gv.w / (1.0f + expf(-gv.w)) * uv.w;
    ((uint2*)oh)[i] = make_uint2(pk_hi(a,b), pk_hi(c,d));
    ((uint2*)ol)[i] = make_uint2(pk_lo(a,b), pk_lo(c,d));
}

// vt planes: vt[(b*H+h)][d][s] = v[b*SEQ+s][h*64+d], hi+lo together
__global__ void transpose_v_bf(const __nv_bfloat16* __restrict__ vh,
                               const __nv_bfloat16* __restrict__ vl,
                               __nv_bfloat16* __restrict__ vth,
                               __nv_bfloat16* __restrict__ vtl)
{
    __shared__ uint32_t t[32][33];
    int bh = blockIdx.z, b = bh >> 4, hh = bh & 15;
    int s0 = blockIdx.x * 32, d0 = blockIdx.y * 32;
    int tx = threadIdx.x, ty = threadIdx.y;    // 32 x 8
    #pragma unroll
    for (int j = 0; j < 32; j += 8) {
        long src = (long)(b * SEQ + s0 + ty + j) * DIMN + hh * HEAD_DIM + d0 + tx;
        uint32_t h16 = *(const uint16_t*)&vh[src];
        uint32_t l16 = *(const uint16_t*)&vl[src];
        t[ty + j][tx] = h16 | (l16 << 16);
    }
    __syncthreads();
    #pragma unroll
    for (int j = 0; j < 32; j += 8) {
        long dst = ((long)bh * HEAD_DIM + d0 + ty + j) * SEQ + s0 + tx;
        uint32_t w = t[tx][ty + j];
        *(uint16_t*)&vth[dst] = (uint16_t)(w & 0xFFFF);
        *(uint16_t*)&vtl[dst] = (uint16_t)(w >> 16);
    }
}

// ---------------- launcher ----------------
extern "C" void kernel_launch(void* const* d_in, const int* in_sizes, int n_in,
                              void* d_out, int out_size)
{
    const int*   tokens  = (const int*)  d_in[0];
    const float* embed   = (const float*)d_in[1];
    const float* Wq      = (const float*)d_in[2];
    const float* Wk      = (const float*)d_in[3];
    const float* Wv      = (const float*)d_in[4];
    const float* Wo      = (const float*)d_in[5];
    const float* Wg      = (const float*)d_in[6];
    const float* Wu      = (const float*)d_in[7];
    const float* Wd      = (const float*)d_in[8];
    const float* ln1     = (const float*)d_in[9];
    const float* ln2     = (const float*)d_in[10];
    const float* norm_w  = (const float*)d_in[11];
    const float* lm_head = (const float*)d_in[12];
    float* out = (float*)d_out;

    float *h, *att, *gate, *up;
    cudaGetSymbolAddress((void**)&h,    g_h);
    cudaGetSymbolAddress((void**)&att,  g_att);
    cudaGetSymbolAddress((void**)&gate, g_gate);
    cudaGetSymbolAddress((void**)&up,   g_up);

    __nv_bfloat16 *xh,*xl,*qh,*ql,*kh_,*kl_,*vh,*vl,*vth,*vtl,*yh,*yl,*ath,*atl,*gh,*gl;
    cudaGetSymbolAddress((void**)&xh,  g_xh);  cudaGetSymbolAddress((void**)&xl,  g_xl);
    cudaGetSymbolAddress((void**)&qh,  g_qh);  cudaGetSymbolAddress((void**)&ql,  g_ql);
    cudaGetSymbolAddress((void**)&kh_, g_kh);  cudaGetSymbolAddress((void**)&kl_, g_kl);
    cudaGetSymbolAddress((void**)&vh,  g_vh);  cudaGetSymbolAddress((void**)&vl,  g_vl);
    cudaGetSymbolAddress((void**)&vth, g_vth); cudaGetSymbolAddress((void**)&vtl, g_vtl);
    cudaGetSymbolAddress((void**)&yh,  g_yh);  cudaGetSymbolAddress((void**)&yl,  g_yl);
    cudaGetSymbolAddress((void**)&ath, g_ath); cudaGetSymbolAddress((void**)&atl, g_atl);
    cudaGetSymbolAddress((void**)&gh,  g_gh);  cudaGetSymbolAddress((void**)&gl,  g_gl);

    __nv_bfloat16 *wqh,*wql,*wkh,*wkl,*wvh,*wvl,*woh,*wol,*wgh,*wgl,*wuh,*wul,*wdh,*wdl,*lmh,*lml;
    cudaGetSymbolAddress((void**)&wqh, g_wq_h); cudaGetSymbolAddress((void**)&wql, g_wq_l);
    cudaGetSymbolAddress((void**)&wkh, g_wk_h); cudaGetSymbolAddress((void**)&wkl, g_wk_l);
    cudaGetSymbolAddress((void**)&wvh, g_wv_h); cudaGetSymbolAddress((void**)&wvl, g_wv_l);
    cudaGetSymbolAddress((void**)&woh, g_wo_h); cudaGetSymbolAddress((void**)&wol, g_wo_l);
    cudaGetSymbolAddress((void**)&wgh, g_wg_h); cudaGetSymbolAddress((void**)&wgl, g_wg_l);
    cudaGetSymbolAddress((void**)&wuh, g_wu_h); cudaGetSymbolAddress((void**)&wul, g_wu_l);
    cudaGetSymbolAddress((void**)&wdh, g_wd_h); cudaGetSymbolAddress((void**)&wdl, g_wd_l);
    cudaGetSymbolAddress((void**)&lmh, g_lm_h); cudaGetSymbolAddress((void**)&lml, g_lm_l);

    const int DYN64  = 4 * (16384 + 64 * 128);    //  98304
    const int DYN128 = 4 * (16384 + 128 * 128);   // 131072
    cudaFuncSetAttribute(bf_gemm<64, 1>,  cudaFuncAttributeMaxDynamicSharedMemorySize, DYN64);
    cudaFuncSetAttribute(bf_gemm<64, 2>,  cudaFuncAttributeMaxDynamicSharedMemorySize, DYN64);
    cudaFuncSetAttribute(bf_gemm<128, 0>, cudaFuncAttributeMaxDynamicSharedMemorySize, DYN128);

    const float scale = 1.0f / sqrtf((float)HEAD_DIM);

    // ---- split weights into bf16 hi/lo planes (once per launch) ----
    split_kernel<<<LAYERS*DIMN*DIMN/1024, 256>>>((const float4*)Wq, (uint2*)wqh, (uint2*)wql);
    split_kernel<<<LAYERS*DIMN*DIMN/1024, 256>>>((const float4*)Wk, (uint2*)wkh, (uint2*)wkl);
    split_kernel<<<LAYERS*DIMN*DIMN/1024, 256>>>((const float4*)Wv, (uint2*)wvh, (uint2*)wvl);
    split_kernel<<<LAYERS*DIMN*DIMN/1024, 256>>>((const float4*)Wo, (uint2*)woh, (uint2*)wol);
    split_kernel<<<LAYERS*HIDDEN*DIMN/1024, 256>>>((const float4*)Wg, (uint2*)wgh, (uint2*)wgl);
    split_kernel<<<LAYERS*HIDDEN*DIMN/1024, 256>>>((const float4*)Wu, (uint2*)wuh, (uint2*)wul);
    split_kernel<<<LAYERS*HIDDEN*DIMN/1024, 256>>>((const float4*)Wd, (uint2*)wdh, (uint2*)wdl);
    split_kernel<<<VOCAB*DIMN/1024, 256>>>((const float4*)lm_head, (uint2*)lmh, (uint2*)lml);

    embed_kernel<<<MTOK, 256>>>(tokens, embed, h);

    dim3 gProj (MTOK / 128, DIMN / 64, 1);             // 16 x 16
    dim3 gFfn  (MTOK / 128, HIDDEN / 128, 1);          // 16 x 32
    dim3 gScore(SEQ / 128, SEQ / 128, BATCH * HEADS);  // 8 x 8 x 32
    dim3 gAV   (SEQ / 128, 1, BATCH * HEADS);          // 8 x 1 x 32
    dim3 gDown (MTOK / 128, DIMN / 64, 1);             // 16 x 16
    dim3 gHead (MTOK / 128, VOCAB / 128, 1);           // 16 x 250
    dim3 gTr   (SEQ / 32, HEAD_DIM / 32, BATCH * HEADS);

    const long DD = (long)DIMN * DIMN, HD = (long)HIDDEN * DIMN;

    for (int l = 0; l < LAYERS; l++) {
        rmsnorm_bf<<<MTOK, 256>>>(h, ln1 + (long)l * DIMN, xh, xl);

        bf_gemm<64, 2><<<gProj, 256, DYN64>>>(xh, xl, DIMN, 0, 0,
            wqh + l * DD, wql + l * DD, DIMN, 0, 0,
            qh, ql, DIMN, 0, 0, DIMN, 1.0f, 1);
        bf_gemm<64, 2><<<gProj, 256, DYN64>>>(xh, xl, DIMN, 0, 0,
            wkh + l * DD, wkl + l * DD, DIMN, 0, 0,
            kh_, kl_, DIMN, 0, 0, DIMN, 1.0f, 1);
        bf_gemm<64, 2><<<gProj, 256, DYN64>>>(xh, xl, DIMN, 0, 0,
            wvh + l * DD, wvl + l * DD, DIMN, 0, 0,
            vh, vl, DIMN, 0, 0, DIMN, 1.0f, 1);

        // att = scale * q k^T
        bf_gemm<128, 0><<<gScore, 256, DYN128>>>(
            qh, ql, DIMN, (long)SEQ * DIMN, HEAD_DIM,
            kh_, kl_, DIMN, (long)SEQ * DIMN, HEAD_DIM,
            att, nullptr, SEQ, (long)HEADS * SEQ * SEQ, (long)SEQ * SEQ,
            HEAD_DIM, scale, HEADS);

        softmax_bf<<<BATCH * HEADS * SEQ, 256>>>(att, ath, atl);
        transpose_v_bf<<<gTr, dim3(32, 8)>>>(vh, vl, vth, vtl);

        // y = att @ v (NT with vt planes)
        bf_gemm<64, 2><<<gAV, 256, DYN64>>>(
            ath, atl, SEQ, (long)HEADS * SEQ * SEQ, (long)SEQ * SEQ,
            vth, vtl, SEQ, (long)HEADS * HEAD_DIM * SEQ, (long)HEAD_DIM * SEQ,
            yh, yl, DIMN, (long)SEQ * DIMN, HEAD_DIM,
            SEQ, 1.0f, HEADS);

        // h += y @ Wo^T
        bf_gemm<64, 1><<<gProj, 256, DYN64>>>(yh, yl, DIMN, 0, 0,
            woh + l * DD, wol + l * DD, DIMN, 0, 0,
            h, nullptr, DIMN, 0, 0, DIMN, 1.0f, 1);

        rmsnorm_bf<<<MTOK, 256>>>(h, ln2 + (long)l * DIMN, xh, xl);

        bf_gemm<128, 0><<<gFfn, 256, DYN128>>>(xh, xl, DIMN, 0, 0,
            wgh + l * HD, wgl + l * HD, DIMN, 0, 0,
            gate, nullptr, HIDDEN, 0, 0, DIMN, 1.0f, 1);
        bf_gemm<128, 0><<<gFfn, 256, DYN128>>>(xh, xl, DIMN, 0, 0,
            wuh + l * HD, wul + l * HD, DIMN, 0, 0,
            up, nullptr, HIDDEN, 0, 0, DIMN, 1.0f, 1);

        silu_bf<<<(MTOK * (long)HIDDEN / 4) / 256, 256>>>(
            (const float4*)gate, (const float4*)up, gh, gl);

        // h += gate @ Wd^T
        bf_gemm<64, 1><<<gDown, 256, DYN64>>>(gh, gl, HIDDEN, 0, 0,
            wdh + l * HD, wdl + l * HD, HIDDEN, 0, 0,
            h, nullptr, DIMN, 0, 0, HIDDEN, 1.0f, 1);
    }

    rmsnorm_bf<<<MTOK, 256>>>(h, norm_w, xh, xl);
    bf_gemm<128, 0><<<gHead, 256, DYN128>>>(xh, xl, DIMN, 0, 0,
        lmh, lml, DIMN, 0, 0,
        out, nullptr, VOCAB, 0, 0, DIMN, 1.0f, 1);
}